// round 12
// baseline (speedup 1.0000x reference)
#include <cuda_runtime.h>

#define NS    1024
#define XD    128
#define HID   256
#define SPLIT 2
#define KHALF (HID / SPLIT)      // 128
#define NBLK  512

typedef unsigned long long u64;
union F2 { u64 u; float f[2]; };

// Scratch (device globals — no allocation allowed)
__device__ float g_px_t[HID * NS];        // pre_x transposed: [k][j]
__device__ u64   g_pyd[HID * NS];         // (pre_y + b1) transposed, dup (v,v): [k][i]
__device__ u64   g_w2p[HID];              // W2 packed (w,w)
__device__ float g_t1p[SPLIT][NS * NS];   // partial T1 sums (8 MB, L2-resident)
__device__ float g_sum_exp;
__device__ float g_sum_diag;
__device__ unsigned g_bar1, g_bar2, g_done;

__device__ __forceinline__ u64 pack2(float lo, float hi) {
    u64 r; asm("mov.b64 %0, {%1, %2};" : "=l"(r) : "f"(lo), "f"(hi)); return r;
}
__device__ __forceinline__ u64 add2(u64 a, u64 b) {
    u64 r; asm("add.rn.f32x2 %0, %1, %2;" : "=l"(r) : "l"(a), "l"(b)); return r;
}
__device__ __forceinline__ u64 fma2(u64 a, u64 b, u64 c) {
    u64 r; asm("fma.rn.f32x2 %0, %1, %2, %3;" : "=l"(r) : "l"(a), "l"(b), "l"(c)); return r;
}
__device__ __forceinline__ u64 relu2(u64 a) {
    F2 v; v.u = a;
    v.f[0] = fmaxf(v.f[0], 0.0f);
    v.f[1] = fmaxf(v.f[1], 0.0f);
    return v.u;
}
__device__ __forceinline__ void cpa16(void* smem, const void* gmem) {
    unsigned s = (unsigned)__cvta_generic_to_shared(smem);
    asm volatile("cp.async.cg.shared.global [%0], [%1], 16;" :: "r"(s), "l"(gmem));
}
__device__ __forceinline__ void cpa_commit() {
    asm volatile("cp.async.commit_group;");
}
template <int N>
__device__ __forceinline__ void cpa_wait() {
    asm volatile("cp.async.wait_group %0;" :: "n"(N));
}
__device__ __forceinline__ unsigned ld_acq(const unsigned* p) {
    unsigned v;
    asm volatile("ld.global.acquire.gpu.u32 %0, [%1];" : "=r"(v) : "l"(p));
    return v;
}

// Shared memory union: max member exactly 48 KB (static smem limit).
union Smem {
    struct {                          // Phase A: 32 KB
        float Ws[XD][64];             // [k][h]
    } a;
    struct {                          // Phase B: 48 KB exactly
        u64   Ys[2][32][64];          // [buf][k][i] (v,v)  32 KB
        float Xs[2][32][64];          // [buf][k][j]        16 KB
    } b;
    struct {                          // Epilogue scratch
        float r1[8], r2[8];
        bool  is_last;
    } c;
};

// ---------------------------------------------------------------------------
// ONE persistent kernel, grid 512 x 256 threads, all blocks co-resident.
// Phase A: pre-GEMMs (16n x 64h slice per block, full K, no chunking).
// Phase B: split-k pairwise partial (64i x 64j x 128k, proven R11 shape).
// Phase C: distributed reduce (add partials, exp, diag) + finalize.
// ---------------------------------------------------------------------------
__global__ void __launch_bounds__(256, 4)
fused_kernel(const float* __restrict__ x,
             const float* __restrict__ y,
             const float* __restrict__ W1,
             const float* __restrict__ b1,
             const float* __restrict__ W2,
             const float* __restrict__ b2,
             float* __restrict__ out) {
    __shared__ Smem sm;

    const int t   = threadIdx.x;       // 0..255
    const int bid = blockIdx.x;        // 0..511

    // ===================== Phase A: pre-GEMM =====================
    {
        const int m  = bid >> 8;                 // 0 = x-matrix, 1 = y-matrix
        const int r  = bid & 255;
        const int n0 = (r >> 2) * 16;
        const int h0 = (r & 3) * 64;
        const float* __restrict__ A = m ? y : x;
        const float* __restrict__ W = W1 + (m ? (XD * HID) : 0);

        if (bid == 0) {
            if (t == 0) { g_sum_exp = 0.0f; g_sum_diag = 0.0f; }
            float w = W2[t];                     // 256 threads == HID
            g_w2p[t] = pack2(w, w);
        }

        // W tile: 128k x 64h = 32 KB via cp.async (no transpose needed).
#pragma unroll
        for (int q = 0; q < 8; q++) {
            int f  = t + q * 256;
            int k  = f >> 4;                     // 0..127
            int c4 = (f & 15) * 4;               // 0..60
            cpa16(&sm.a.Ws[k][c4], &W[k * HID + h0 + c4]);
        }
        cpa_commit();
        cpa_wait<0>();
        __syncthreads();

        // Micro: h-pair (packed) x 2 n. A rows via broadcast LDG (L1-hot).
        const int hp = t & 31;                   // h = h0 + hp*2 + {0,1}
        const int ng = t >> 5;                   // n = n0 + ng*2 + {0,1}
        const float* a0p = &A[(n0 + ng * 2)     * XD];
        const float* a1p = &A[(n0 + ng * 2 + 1) * XD];

        u64 acc0 = 0ull, acc1 = 0ull;
#pragma unroll 8
        for (int k = 0; k < XD; k++) {
            u64 wv = *(const u64*)&sm.a.Ws[k][hp * 2];
            float a0 = __ldg(&a0p[k]);
            float a1 = __ldg(&a1p[k]);
            acc0 = fma2(pack2(a0, a0), wv, acc0);
            acc1 = fma2(pack2(a1, a1), wv, acc1);
        }

        F2 v0, v1; v0.u = acc0; v1.u = acc1;
        if (m == 0) {
#pragma unroll
            for (int hl = 0; hl < 2; hl++) {
                int h = h0 + hp * 2 + hl;
                g_px_t[h * NS + n0 + ng * 2]     = v0.f[hl];
                g_px_t[h * NS + n0 + ng * 2 + 1] = v1.f[hl];
            }
        } else {
#pragma unroll
            for (int hl = 0; hl < 2; hl++) {
                int h = h0 + hp * 2 + hl;
                float bias = b1[h];
                float w0 = v0.f[hl] + bias;
                float w1 = v1.f[hl] + bias;
                *(ulonglong2*)&g_pyd[h * NS + n0 + ng * 2] =
                    make_ulonglong2(pack2(w0, w0), pack2(w1, w1));
            }
        }
    }

    // ============ Barrier 1 (all 512 blocks co-resident) ============
    __threadfence();
    __syncthreads();
    if (t == 0) {
        atomicAdd(&g_bar1, 1u);
        while (ld_acq(&g_bar1) < NBLK) __nanosleep(40);
    }
    __syncthreads();

    // ===================== Phase B: split-k pairwise =====================
    {
        const int s  = bid >> 8;
        const int tb = bid & 255;
        const int bi = (tb >> 4) * 64;
        const int bj = (tb & 15) * 64;
        const int k0 = s * KHALF;
        const int gi = t >> 4;                   // i = bi + gi*4 + a
        const int gj = t & 15;                   // j = bj + gj*4 (2 f32x2 pairs)

        auto load_stage = [&](int buf, int kk) {
            // Ys: 32k x 64i u64 = 1024 x 16B; 4 per thread.
#pragma unroll
            for (int q = 0; q < 4; q++) {
                int f  = t + q * 256;
                int k  = f >> 5;
                int c2 = (f & 31) * 2;
                cpa16(&sm.b.Ys[buf][k][c2], &g_pyd[(k0 + kk + k) * NS + bi + c2]);
            }
            // Xs: 32k x 64j float = 512 x 16B; 2 per thread.
#pragma unroll
            for (int q = 0; q < 2; q++) {
                int f  = t + q * 256;
                int k  = f >> 4;
                int c4 = (f & 15) * 4;
                cpa16(&sm.b.Xs[buf][k][c4], &g_px_t[(k0 + kk + k) * NS + bj + c4]);
            }
            cpa_commit();
        };

        u64 acc[4][2];
#pragma unroll
        for (int a = 0; a < 4; a++) { acc[a][0] = 0ull; acc[a][1] = 0ull; }

        load_stage(0, 0);

        const int NCHUNK = KHALF / 32;           // 4
        for (int it = 0; it < NCHUNK; it++) {
            const int cur = it & 1;
            if (it + 1 < NCHUNK) {
                load_stage(cur ^ 1, (it + 1) * 32);
                cpa_wait<1>();
            } else {
                cpa_wait<0>();
            }
            __syncthreads();

            const int kk = it * 32;
#pragma unroll 8
            for (int k = 0; k < 32; k++) {
                ulonglong2 ya = *(const ulonglong2*)&sm.b.Ys[cur][k][gi * 4];
                ulonglong2 yb = *(const ulonglong2*)&sm.b.Ys[cur][k][gi * 4 + 2];
                ulonglong2 xv = *(const ulonglong2*)&sm.b.Xs[cur][k][gj * 4];
                u64 w = __ldg(&g_w2p[k0 + kk + k]);   // broadcast, L1-hot
                u64 yp[4] = {ya.x, ya.y, yb.x, yb.y};
                u64 xp[2] = {xv.x, xv.y};
#pragma unroll
                for (int a = 0; a < 4; a++)
#pragma unroll
                    for (int p = 0; p < 2; p++) {
                        u64 sum = relu2(add2(yp[a], xp[p]));
                        acc[a][p] = fma2(sum, w, acc[a][p]);
                    }
            }
            __syncthreads();
        }

        // Write partial tile: row i, 4 consecutive j as one 16B store.
#pragma unroll
        for (int a = 0; a < 4; a++) {
            int i = bi + gi * 4 + a;
            *(ulonglong2*)&g_t1p[s][i * NS + bj + gj * 4] =
                make_ulonglong2(acc[a][0], acc[a][1]);
        }
    }

    // ============ Barrier 2 ============
    __threadfence();
    __syncthreads();
    if (t == 0) {
        atomicAdd(&g_bar2, 1u);
        while (ld_acq(&g_bar2) < NBLK) __nanosleep(40);
    }
    __syncthreads();

    // ===================== Phase C: reduce =====================
    {
        const float c = b2[0] - 1.0f;
        const float4* P0 = (const float4*)g_t1p[0];
        const float4* P1 = (const float4*)g_t1p[1];

        float sexp = 0.0f, sdiag = 0.0f;
#pragma unroll
        for (int q = 0; q < 2; q++) {
            int fi = bid * 512 + q * 256 + t;    // 0..262143
            float4 A4 = P0[fi];
            float4 B4 = P1[fi];
            float v0 = A4.x + B4.x + c;
            float v1 = A4.y + B4.y + c;
            float v2 = A4.z + B4.z + c;
            float v3 = A4.w + B4.w + c;
            sexp += __expf(v0) + __expf(v1) + __expf(v2) + __expf(v3);

            int g = fi * 4;
            int i = g >> 10;
            int j = g & 1023;                    // j % 4 == 0; row not crossed
            int d = i - j;
            if (d >= 0 && d < 4)
                sdiag += (d == 0) ? v0 : (d == 1) ? v1 : (d == 2) ? v2 : v3;
        }

        const int lane = t & 31, wid = t >> 5;
#pragma unroll
        for (int o = 16; o > 0; o >>= 1) {
            sexp  += __shfl_down_sync(0xFFFFFFFFu, sexp,  o);
            sdiag += __shfl_down_sync(0xFFFFFFFFu, sdiag, o);
        }
        if (lane == 0) { sm.c.r1[wid] = sexp; sm.c.r2[wid] = sdiag; }
        __syncthreads();
        if (t == 0) {
            float s1 = 0.0f, s2 = 0.0f;
#pragma unroll
            for (int w = 0; w < 8; w++) { s1 += sm.c.r1[w]; s2 += sm.c.r2[w]; }
            atomicAdd(&g_sum_exp,  s1);
            atomicAdd(&g_sum_diag, s2);
            __threadfence();
            unsigned v = atomicAdd(&g_done, 1u);
            sm.c.is_last = (v == NBLK - 1);
        }
        __syncthreads();

        if (sm.c.is_last && t == 0) {
            // Reset all counters for the next graph replay, then finalize.
            g_done = 0;
            g_bar1 = 0;
            g_bar2 = 0;
            float n = (float)NS;
            float se = __ldcg(&g_sum_exp);
            float sd = __ldcg(&g_sum_diag);
            out[0] = (sd + n) / n - se / (n * n);
        }
    }
}

// ---------------------------------------------------------------------------
extern "C" void kernel_launch(void* const* d_in, const int* in_sizes, int n_in,
                              void* d_out, int out_size) {
    const float* x  = (const float*)d_in[0];
    const float* y  = (const float*)d_in[1];
    const float* W1 = (const float*)d_in[2];
    const float* b1 = (const float*)d_in[3];
    const float* W2 = (const float*)d_in[4];
    const float* b2 = (const float*)d_in[5];
    float* out = (float*)d_out;

    fused_kernel<<<NBLK, 256>>>(x, y, W1, b1, W2, b2, out);
}